// round 17
// baseline (speedup 1.0000x reference)
#include <cuda_runtime.h>
#include <cuda_fp16.h>
#include <cstdint>

#define N_NODES_MAX 50000
#define NODE_DIM    128
#define HIDDEN      256
#define NCOLS       1024

// Table column layout: [0:256)=seg0 (p1 row), [256:512)=seg2 (p2 row),
//                      [512:768)=seg1 (p1 col), [768:1024)=seg3 (p2 col)

__device__ __half g_table[(size_t)N_NODES_MAX * NCOLS];   // 102.4 MB
__device__ __half g_Xh[(size_t)N_NODES_MAX * NODE_DIM];   // 12.8 MB
__device__ __half g_WTh[NCOLS * NODE_DIM];                // [n][k] permuted
__device__ __half g_ch[HIDDEN];
__device__ __half g_w2h[HIDDEN];
__device__ int    g_is64;

__device__ __forceinline__ uint32_t smem_u32(const void* p) {
    uint32_t a;
    asm("{ .reg .u64 t; cvta.to.shared.u64 t, %1; cvt.u32.u64 %0, t; }" : "=r"(a) : "l"(p));
    return a;
}
__device__ __forceinline__ void ldsm_x4(uint32_t& r0, uint32_t& r1, uint32_t& r2, uint32_t& r3,
                                        uint32_t addr) {
    asm volatile("ldmatrix.sync.aligned.m8n8.x4.shared.b16 {%0,%1,%2,%3}, [%4];"
                 : "=r"(r0), "=r"(r1), "=r"(r2), "=r"(r3) : "r"(addr));
}
// fp16-accumulate MMA (2 C regs)
__device__ __forceinline__ void mma16816_h(uint32_t* c, const uint32_t* a,
                                           uint32_t b0, uint32_t b1) {
    asm volatile("mma.sync.aligned.m16n8k16.row.col.f16.f16.f16.f16 "
                 "{%0,%1}, {%2,%3,%4,%5}, {%6,%7}, {%0,%1};"
                 : "+r"(c[0]), "+r"(c[1])
                 : "r"(a[0]), "r"(a[1]), "r"(a[2]), "r"(a[3]), "r"(b0), "r"(b1));
}
#define CP16(dst, src) \
    asm volatile("cp.async.cg.shared.global [%0], [%1], 16;" :: "r"(dst), "l"(src))
#define CP16P(dst, src, p) \
    asm volatile("{ .reg .pred q; setp.ne.b32 q, %2, 0;\n\t" \
                 "@q cp.async.cg.shared.global [%0], [%1], 16; }" \
                 :: "r"(dst), "l"(src), "r"(p))
#define CP_COMMIT  asm volatile("cp.async.commit_group;")
#define CP_WAIT1   asm volatile("cp.async.wait_group 1;")

// ---------------------------------------------------------------------------
// Fused prep (unchanged champion)
// ---------------------------------------------------------------------------
__global__ void prep_all_kernel(const float* __restrict__ X,
                                const float* __restrict__ W1, const float* __restrict__ b1,
                                const float* __restrict__ gamma, const float* __restrict__ beta,
                                const float* __restrict__ mean, const float* __restrict__ var,
                                const float* __restrict__ W2,
                                const int* __restrict__ idx32, int nx, int total4) {
    int b = blockIdx.x;
    int tid = threadIdx.x;
    if (b < 512) {
        int i = b * 256 + tid;
        int n = i >> 7;
        int k = i & 127;
        int h = n & 255;
        int grp = n >> 8;
        int srcRow;
        if (grp == 0)      srcRow = k;
        else if (grp == 1) srcRow = k + 16;
        else if (grp == 2) srcRow = 128 + k;
        else               srcRow = (k + 144) & 255;
        float s = gamma[h] * rsqrtf(var[h] + 1e-5f);
        g_WTh[i] = __float2half_rn(W1[srcRow * 256 + h] * s);
    } else if (b < 512 + nx) {
        int i = (b - 512) * 256 + tid;
        if (i < total4) {
            float4 v = *(const float4*)(X + i * 4);
            __half2* dst = (__half2*)(g_Xh + i * 4);
            dst[0] = __floats2half2_rn(v.x, v.y);
            dst[1] = __floats2half2_rn(v.z, v.w);
        }
    } else {
        if (tid < HIDDEN) {
            float s = gamma[tid] * rsqrtf(var[tid] + 1e-5f);
            g_ch[tid] = __float2half_rn(b1[tid] * s + beta[tid] - mean[tid] * s);
            g_w2h[tid] = __float2half_rn(W2[tid]);
        }
        if (tid < 32) {
            int acc = 0;
            for (int i = tid; i < 1024; i += 32) acc |= idx32[2 * i + 1];
            #pragma unroll
            for (int s = 16; s; s >>= 1) acc |= __shfl_xor_sync(0xFFFFFFFFu, acc, s);
            if (tid == 0) g_is64 = (acc == 0) ? 1 : 0;
        }
    }
}

// ---------------------------------------------------------------------------
// Persistent warp-MMA fp16 GEMM, warp tile 64Mx32N, B fragments HOISTED to
// registers (tile-invariant), f16 accumulators. Mainloop = 4 A-LDSM + 16 MMA.
// ---------------------------------------------------------------------------
#define BM 128
#define BN 128
#define SM_B    0
#define SM_A    32768
#define A_STAGE 32768
#define SM_TOTAL 98304
#define STG_STRIDE 272

__global__ __launch_bounds__(256, 1) void gemm_mma_kernel(int M) {
    extern __shared__ char smem[];
    uint32_t sb = smem_u32(smem);
    int tid = threadIdx.x;
    int lane = tid & 31;
    int wid = tid >> 5;
    int wm = wid & 1;      // 2 warps over M (64 rows each)
    int wn = wid >> 1;     // 4 warps over N (32 cols each)
    int bn = blockIdx.x * BN;
    int y = blockIdx.y;
    int NY = gridDim.y;
    int totTiles = (M + BM - 1) / BM;

    // B tile (128 n-rows x 128 k) swizzled (group 0)
    for (int s = tid; s < 2048; s += 256) {
        int row = s >> 4;
        int c = s & 15;
        uint32_t off = (uint32_t)(row * 256 + ((c ^ (row & 7)) << 4));
        CP16(sb + SM_B + off, (const char*)(g_WTh + (size_t)(bn + row) * 128 + c * 8));
    }
    CP_COMMIT;

    auto prefetchA = [&](int t, int st) {
        int bm = t * BM;
        uint32_t base = sb + SM_A + st * A_STAGE;
        for (int s = tid; s < 2048; s += 256) {
            int row = s >> 4;
            int c = s & 15;
            int gr = bm + row;
            int valid = (gr < M) ? 1 : 0;
            uint32_t off = (uint32_t)(row * 256 + ((c ^ (row & 7)) << 4));
            CP16P(base + off, (const char*)(g_Xh + (size_t)gr * 128 + c * 8), valid);
        }
        CP_COMMIT;
    };

    if (y < totTiles) prefetchA(y, 0); else CP_COMMIT;

    int aR = (lane & 15);
    int aC = lane >> 4;
    int bR = (lane & 7) + ((lane >> 4) << 3);
    int bC = (lane >> 3) & 1;

    // ---- hoist ALL B fragments (tile-invariant): 8 ks x 2 np x 4 = 64 regs
    CP_WAIT1;            // B done (A0 may be pending)
    __syncthreads();
    uint32_t bfr[8][2][4];
    #pragma unroll
    for (int ks = 0; ks < 8; ks++) {
        #pragma unroll
        for (int np = 0; np < 2; np++) {
            int row = wn * 32 + np * 16 + bR;
            int ch = ks * 2 + bC;
            uint32_t off = (uint32_t)(row * 256 + ((ch ^ (row & 7)) << 4));
            ldsm_x4(bfr[ks][np][0], bfr[ks][np][1], bfr[ks][np][2], bfr[ks][np][3],
                    sb + SM_B + off);
        }
    }

    int i = 0;
    for (int t = y; t < totTiles; t += NY, i++) {
        int tn = t + NY;
        if (tn < totTiles) prefetchA(tn, (i + 1) & 1); else CP_COMMIT;
        CP_WAIT1;
        __syncthreads();

        uint32_t aBase = sb + SM_A + (i & 1) * A_STAGE;

        // f16 accumulators: 4 mt x 4 nt x 2 regs = 32
        uint32_t acc[4][4][2];
        #pragma unroll
        for (int mt = 0; mt < 4; mt++)
            #pragma unroll
            for (int nt = 0; nt < 4; nt++) {
                acc[mt][nt][0] = 0u;
                acc[mt][nt][1] = 0u;
            }

        #pragma unroll
        for (int ks = 0; ks < 8; ks++) {
            uint32_t a[4][4];
            #pragma unroll
            for (int mt = 0; mt < 4; mt++) {
                int row = wm * 64 + mt * 16 + aR;
                int ch = ks * 2 + aC;
                uint32_t off = (uint32_t)(row * 256 + ((ch ^ (row & 7)) << 4));
                ldsm_x4(a[mt][0], a[mt][1], a[mt][2], a[mt][3], aBase + off);
            }
            #pragma unroll
            for (int mt = 0; mt < 4; mt++)
                #pragma unroll
                for (int nt = 0; nt < 4; nt++) {
                    int np = nt >> 1, qp = (nt & 1) * 2;
                    mma16816_h(acc[mt][nt], a[mt], bfr[ks][np][qp], bfr[ks][np][qp + 1]);
                }
        }

        // staged writeback: pass p handles rows [p*64, p*64+64) = warps wm==p
        int bm = t * BM;
        char* stg = smem + SM_A + (i & 1) * A_STAGE;
        #pragma unroll
        for (int p = 0; p < 2; p++) {
            __syncthreads();
            if (wm == p) {
                #pragma unroll
                for (int mt = 0; mt < 4; mt++)
                    #pragma unroll
                    for (int h = 0; h < 2; h++) {
                        int lr = mt * 16 + (lane >> 2) + h * 8;
                        char* rowp = stg + lr * STG_STRIDE + wn * 64 + (lane & 3) * 4;
                        #pragma unroll
                        for (int nt = 0; nt < 4; nt++)
                            *(uint32_t*)(rowp + nt * 16) = acc[mt][nt][h];
                    }
            }
            __syncthreads();
            for (int s = tid; s < 1024; s += 256) {
                int lr = s >> 4;
                int c = s & 15;
                int gr = bm + p * 64 + lr;
                if (gr < M)
                    *(uint4*)(g_table + (size_t)gr * NCOLS + bn + c * 8) =
                        *(const uint4*)(stg + lr * STG_STRIDE + c * 16);
            }
        }
        __syncthreads();
    }
}

// ---------------------------------------------------------------------------
// Edge kernel: R11 champion shape — 2 edges/warp, ALL 8 gathers upfront,
// packed half2 MLP.
// ---------------------------------------------------------------------------
__global__ __launch_bounds__(256) void edge_kernel(const void* __restrict__ idx,
                                                   const float* __restrict__ b2,
                                                   float* __restrict__ out, int E) {
    int lane = threadIdx.x & 31;
    int e0 = blockIdx.x * 16 + (threadIdx.x >> 5) * 2;
    if (e0 >= E) return;
    bool has2 = (e0 + 1 < E);
    int e1 = has2 ? e0 + 1 : e0;

    int r0, c0, r1, c1;
    if (g_is64) {
        const long long* p = (const long long*)idx;
        r0 = (int)p[e0]; c0 = (int)p[E + e0];
        r1 = (int)p[e1]; c1 = (int)p[E + e1];
    } else {
        const int* p = (const int*)idx;
        r0 = p[e0]; c0 = p[E + e0];
        r1 = p[e1]; c1 = p[E + e1];
    }

    const __half* Tr0 = g_table + (size_t)r0 * NCOLS;
    const __half* Tc0 = g_table + (size_t)c0 * NCOLS;
    const __half* Tr1 = g_table + (size_t)r1 * NCOLS;
    const __half* Tc1 = g_table + (size_t)c1 * NCOLS;
    int o = lane * 8;

    uint4 a0 = *(const uint4*)(Tr0 + o);
    uint4 a2 = *(const uint4*)(Tr0 + 256 + o);
    uint4 b1v = *(const uint4*)(Tc0 + 512 + o);
    uint4 b3 = *(const uint4*)(Tc0 + 768 + o);
    uint4 d0 = *(const uint4*)(Tr1 + o);
    uint4 d2 = *(const uint4*)(Tr1 + 256 + o);
    uint4 f1 = *(const uint4*)(Tc1 + 512 + o);
    uint4 f3 = *(const uint4*)(Tc1 + 768 + o);

    uint4 chv = *(const uint4*)(g_ch + o);
    uint4 whv = *(const uint4*)(g_w2h + o);

    const __half2* ch = (const __half2*)&chv;
    const __half2* wh = (const __half2*)&whv;
    const __half2* pa0 = (const __half2*)&a0;  const __half2* pa2 = (const __half2*)&a2;
    const __half2* pb1 = (const __half2*)&b1v; const __half2* pb3 = (const __half2*)&b3;
    const __half2* pd0 = (const __half2*)&d0;  const __half2* pd2 = (const __half2*)&d2;
    const __half2* pf1 = (const __half2*)&f1;  const __half2* pf3 = (const __half2*)&f3;

    const __half2 zero = __float2half2_rn(0.f);
    __half2 accA = zero, accB = zero;
    #pragma unroll
    for (int j = 0; j < 4; j++) {
        __half2 z1 = __hadd2(__hadd2(pa0[j], pb1[j]), ch[j]);
        accA = __hfma2(__hmax2(z1, zero), wh[j], accA);
        __half2 z2 = __hadd2(__hadd2(pa2[j], pb3[j]), ch[j]);
        accA = __hfma2(__hmax2(z2, zero), wh[j], accA);
        __half2 y1 = __hadd2(__hadd2(pd0[j], pf1[j]), ch[j]);
        accB = __hfma2(__hmax2(y1, zero), wh[j], accB);
        __half2 y2 = __hadd2(__hadd2(pd2[j], pf3[j]), ch[j]);
        accB = __hfma2(__hmax2(y2, zero), wh[j], accB);
    }
    float2 fA = __half22float2(accA);
    float2 fB = __half22float2(accB);
    float sA = fA.x + fA.y;
    float sB = fB.x + fB.y;

    #pragma unroll
    for (int s = 16; s; s >>= 1) {
        sA += __shfl_xor_sync(0xFFFFFFFFu, sA, s);
        sB += __shfl_xor_sync(0xFFFFFFFFu, sB, s);
    }

    if (lane == 0) {
        float bb = b2[0];
        float x = sA * 0.5f + bb;
        out[e0] = 1.f / (1.f + expf(-x));
        if (has2) {
            float x2 = sB * 0.5f + bb;
            out[e0 + 1] = 1.f / (1.f + expf(-x2));
        }
    }
}

// ---------------------------------------------------------------------------
extern "C" void kernel_launch(void* const* d_in, const int* in_sizes, int n_in,
                              void* d_out, int out_size) {
    const float* node_feat = (const float*)d_in[0];
    const void*  eidx      = d_in[1];
    const float* W1        = (const float*)d_in[2];
    const float* b1        = (const float*)d_in[3];
    const float* gamma     = (const float*)d_in[4];
    const float* beta      = (const float*)d_in[5];
    const float* mean      = (const float*)d_in[6];
    const float* var       = (const float*)d_in[7];
    const float* W2        = (const float*)d_in[8];
    const float* b2        = (const float*)d_in[9];
    float* out = (float*)d_out;

    int M = in_sizes[0] / NODE_DIM;   // 50000
    int E = out_size;                 // 300000

    cudaFuncSetAttribute(gemm_mma_kernel, cudaFuncAttributeMaxDynamicSharedMemorySize, SM_TOTAL);

    int total4 = M * NODE_DIM / 4;
    int nx = (total4 + 255) / 256;
    prep_all_kernel<<<513 + nx, 256>>>(node_feat, W1, b1, gamma, beta, mean, var, W2,
                                       (const int*)eidx, nx, total4);

    dim3 ggrid(NCOLS / BN, 37);   // (8,37) = 296 CTAs
    gemm_mma_kernel<<<ggrid, 256, SM_TOTAL>>>(M);

    edge_kernel<<<(E + 15) / 16, 256>>>(eidx, b2, out, E);
}